// round 7
// baseline (speedup 1.0000x reference)
#include <cuda_runtime.h>
#include <cuda_bf16.h>
#include <cstdint>

#define L_   197
#define LP_  200
#define NB_  128
#define E_   768
#define H_   12
#define HD_  64
#define B_   1536
#define NS_  60
#define LT_  257
#define OUT_ELEMS 25264128
#define AW_ELEMS  6480512

#define STR2 72        // smem row stride (halfs) for qk/av 64-wide tiles

#define IN_ELEMS 19365888        // 25216*768
#define W_ELEMS  589824          // 768*768

// stage layout for pipelined GEMM (bytes)
#define OFFA_H 0
#define OFFA_L 10240
#define OFFB_H 20480
#define OFFB_L 30720
#define STAGE_BYTES 40960
#define SMEM_GEMM (2*STAGE_BYTES)

// ---------------- scratch ----------------
__device__ float g_q[19365888];
__device__ float g_k[19365888];
__device__ float g_v[19365888];
__device__ float g_attn[78950400];           // (B, LT, LP_)
__device__ __nv_bfloat16 g_in_h[3*IN_ELEMS]; // split q,k,v inputs
__device__ __nv_bfloat16 g_in_l[3*IN_ELEMS];
__device__ __nv_bfloat16 g_w_h[4*W_ELEMS];   // split ipw(3) + opw(1)
__device__ __nv_bfloat16 g_w_l[4*W_ELEMS];
__device__ __nv_bfloat16 g_xh[OUT_ELEMS];    // split AV output
__device__ __nv_bfloat16 g_xl[OUT_ELEMS];

// ================= helpers =================
__device__ __forceinline__ uint32_t smem_u32(const void* p){
    return (uint32_t)__cvta_generic_to_shared(p);
}
__device__ __forceinline__ void ldsm_x4(uint32_t* r, uint32_t addr){
    asm volatile("ldmatrix.sync.aligned.m8n8.x4.shared.b16 {%0,%1,%2,%3}, [%4];"
        : "=r"(r[0]),"=r"(r[1]),"=r"(r[2]),"=r"(r[3]) : "r"(addr));
}
__device__ __forceinline__ void mma_bf16(float* d, const uint32_t* a, const uint32_t* b){
    asm volatile("mma.sync.aligned.m16n8k16.row.col.f32.bf16.bf16.f32 "
        "{%0,%1,%2,%3}, {%4,%5,%6,%7}, {%8,%9}, {%0,%1,%2,%3};"
        : "+f"(d[0]),"+f"(d[1]),"+f"(d[2]),"+f"(d[3])
        : "r"(a[0]),"r"(a[1]),"r"(a[2]),"r"(a[3]), "r"(b[0]),"r"(b[1]));
}
__device__ __forceinline__ void cp16(uint32_t dst, const void* src){
    asm volatile("cp.async.cg.shared.global [%0], [%1], 16;" :: "r"(dst), "l"(src));
}
#define CP_COMMIT() asm volatile("cp.async.commit_group;")
#define CP_WAIT(n)  asm volatile("cp.async.wait_group %0;" :: "n"(n))

// ---------------- 0. split fp32 -> bf16 hi/lo ----------------
__global__ __launch_bounds__(256) void split_kernel(
    const float* __restrict__ src, __nv_bfloat16* __restrict__ dh,
    __nv_bfloat16* __restrict__ dl, int n4)
{
    int i = blockIdx.x * 256 + threadIdx.x;
    if (i >= n4) return;
    float4 f = ((const float4*)src)[i];
    __nv_bfloat162 h01 = __floats2bfloat162_rn(f.x, f.y);
    __nv_bfloat162 h23 = __floats2bfloat162_rn(f.z, f.w);
    __nv_bfloat162 l01 = __floats2bfloat162_rn(f.x - __bfloat162float(h01.x),
                                               f.y - __bfloat162float(h01.y));
    __nv_bfloat162 l23 = __floats2bfloat162_rn(f.z - __bfloat162float(h23.x),
                                               f.w - __bfloat162float(h23.y));
    *(uint2*)(dh + 4*(size_t)i) = make_uint2(*(uint32_t*)&h01, *(uint32_t*)&h23);
    *(uint2*)(dl + 4*(size_t)i) = make_uint2(*(uint32_t*)&l01, *(uint32_t*)&l23);
}

// ---------------- pipelined GEMM mainloop (pre-split bf16 inputs) ----------------
__device__ __forceinline__ void prefetch_chunk(
    const __nv_bfloat16* __restrict__ Ah, const __nv_bfloat16* __restrict__ Al,
    const __nv_bfloat16* __restrict__ Bh, const __nv_bfloat16* __restrict__ Bl,
    uint32_t sbase, int kBase, int tid)
{
    #pragma unroll
    for (int j = 0; j < 2; j++){
        int idx = j*256 + tid;            // < 512
        int row = idx >> 2, kp = idx & 3;
        uint32_t doff = (uint32_t)(row*80 + kp*16);
        size_t soff = (size_t)row*E_ + kBase + kp*8;
        cp16(sbase + OFFA_H + doff, Ah + soff);
        cp16(sbase + OFFA_L + doff, Al + soff);
        cp16(sbase + OFFB_H + doff, Bh + soff);
        cp16(sbase + OFFB_L + doff, Bl + soff);
    }
}

__device__ __forceinline__ void gemm_body_pre(
    const __nv_bfloat16* __restrict__ Ah, const __nv_bfloat16* __restrict__ Al,
    const __nv_bfloat16* __restrict__ Bh, const __nv_bfloat16* __restrict__ Bl,
    uint32_t smb, float acc[2][8][4], int tid)
{
    int lane = tid & 31, wid = tid >> 5;
    int wm = (wid & 3) * 32, wn = (wid >> 2) * 64;

    uint32_t oA = (uint32_t)((wm + (lane & 15))*80 + (lane >> 4)*16);
    int rowB = wn + (lane & 7) + ((lane >> 4) & 1)*8;
    uint32_t oB = (uint32_t)(rowB*80 + ((lane >> 3) & 1)*16);

    prefetch_chunk(Ah, Al, Bh, Bl, smb, 0, tid);
    CP_COMMIT();

    for (int ch = 0; ch < 24; ch++){
        uint32_t st = smb + (uint32_t)(ch & 1)*STAGE_BYTES;
        if (ch + 1 < 24){
            prefetch_chunk(Ah, Al, Bh, Bl, smb + (uint32_t)((ch+1) & 1)*STAGE_BYTES,
                           (ch+1)*32, tid);
            CP_COMMIT();
            CP_WAIT(1);
        } else {
            CP_WAIT(0);
        }
        __syncthreads();

        uint32_t aAh = st + OFFA_H + oA, aAl = st + OFFA_L + oA;
        uint32_t aBh = st + OFFB_H + oB, aBl = st + OFFB_L + oB;

        #pragma unroll
        for (int ks = 0; ks < 2; ks++){
            uint32_t ah0[4], ah1[4], al0[4], al1[4];
            ldsm_x4(ah0, aAh + ks*32);
            ldsm_x4(ah1, aAh + ks*32 + 16*80);
            ldsm_x4(al0, aAl + ks*32);
            ldsm_x4(al1, aAl + ks*32 + 16*80);
            #pragma unroll
            for (int q = 0; q < 4; q++){
                uint32_t bh[4], bl[4];
                ldsm_x4(bh, aBh + ks*32 + q*16*80);
                ldsm_x4(bl, aBl + ks*32 + q*16*80);
                mma_bf16(acc[0][2*q],   ah0, bh);
                mma_bf16(acc[0][2*q+1], ah0, bh+2);
                mma_bf16(acc[0][2*q],   ah0, bl);
                mma_bf16(acc[0][2*q+1], ah0, bl+2);
                mma_bf16(acc[0][2*q],   al0, bh);
                mma_bf16(acc[0][2*q+1], al0, bh+2);
                mma_bf16(acc[1][2*q],   ah1, bh);
                mma_bf16(acc[1][2*q+1], ah1, bh+2);
                mma_bf16(acc[1][2*q],   ah1, bl);
                mma_bf16(acc[1][2*q+1], ah1, bl+2);
                mma_bf16(acc[1][2*q],   al1, bh);
                mma_bf16(acc[1][2*q+1], al1, bh+2);
            }
        }
        __syncthreads();
    }
}

// ---------------- 1. QKV projection ----------------
__global__ __launch_bounds__(256, 2) void proj_tc(
    const float* __restrict__ bias)
{
    extern __shared__ __align__(16) char sm[];
    int tid = threadIdx.x, lane = tid & 31, wid = tid >> 5;
    int p = blockIdx.z;
    const __nv_bfloat16* Ah = g_in_h + (size_t)p*IN_ELEMS;
    const __nv_bfloat16* Al = g_in_l + (size_t)p*IN_ELEMS;
    const __nv_bfloat16* Bh = g_w_h + (size_t)p*W_ELEMS;
    const __nv_bfloat16* Bl = g_w_l + (size_t)p*W_ELEMS;
    const float* bp = bias + (size_t)p*E_;
    float* outp     = (p==0) ? g_q : ((p==1) ? g_k : g_v);
    float scale     = (p==0) ? 0.125f : 1.0f;

    int l = blockIdx.y;
    int nBase = blockIdx.x * 128;
    size_t mBase = (size_t)l * 128;

    float acc[2][8][4];
    #pragma unroll
    for (int i=0;i<2;i++)
        #pragma unroll
        for (int j=0;j<8;j++)
            #pragma unroll
            for (int c=0;c<4;c++) acc[i][j][c] = 0.f;

    gemm_body_pre(Ah + mBase*E_, Al + mBase*E_, Bh + (size_t)nBase*E_, Bl + (size_t)nBase*E_,
                  smem_u32(sm), acc, tid);

    int wm = (wid & 3) * 32, wn = (wid >> 2) * 64;
    #pragma unroll
    for (int mi = 0; mi < 2; mi++){
        int r = wm + mi*16 + (lane >> 2);
        #pragma unroll
        for (int ni = 0; ni < 8; ni++){
            int col = wn + ni*8 + (lane & 3)*2;
            int gc  = nBase + col;
            int h = gc >> 6, d = gc & 63;
            float b0 = bp[gc], b1 = bp[gc+1];
            float2 v0 = make_float2((acc[mi][ni][0] + b0)*scale, (acc[mi][ni][1] + b1)*scale);
            float2 v1 = make_float2((acc[mi][ni][2] + b0)*scale, (acc[mi][ni][3] + b1)*scale);
            *(float2*)&outp[(((size_t)(r*H_ + h))*L_ + l)*HD_ + d] = v0;
            *(float2*)&outp[(((size_t)((r+8)*H_ + h))*L_ + l)*HD_ + d] = v1;
        }
    }
}

// ---------------- 6. out projection ----------------
__global__ __launch_bounds__(256, 2) void out_tc(
    const float* __restrict__ bias, float* __restrict__ outp)
{
    extern __shared__ __align__(16) char sm[];
    int tid = threadIdx.x, lane = tid & 31, wid = tid >> 5;
    size_t mBase = (size_t)blockIdx.y * 128;
    int nBase = blockIdx.x * 128;

    float acc[2][8][4];
    #pragma unroll
    for (int i=0;i<2;i++)
        #pragma unroll
        for (int j=0;j<8;j++)
            #pragma unroll
            for (int c=0;c<4;c++) acc[i][j][c] = 0.f;

    gemm_body_pre(g_xh + mBase*E_, g_xl + mBase*E_,
                  g_w_h + (size_t)3*W_ELEMS + (size_t)nBase*E_,
                  g_w_l + (size_t)3*W_ELEMS + (size_t)nBase*E_,
                  smem_u32(sm), acc, tid);

    int wm = (wid & 3) * 32, wn = (wid >> 2) * 64;
    #pragma unroll
    for (int mi = 0; mi < 2; mi++){
        int r = wm + mi*16 + (lane >> 2);
        #pragma unroll
        for (int ni = 0; ni < 8; ni++){
            int col = wn + ni*8 + (lane & 3)*2;
            int gc  = nBase + col;
            float b0 = bias[gc], b1 = bias[gc+1];
            float2 v0 = make_float2(acc[mi][ni][0] + b0, acc[mi][ni][1] + b1);
            float2 v1 = make_float2(acc[mi][ni][2] + b0, acc[mi][ni][3] + b1);
            *(float2*)&outp[(mBase + r)*E_ + gc] = v0;
            *(float2*)&outp[(mBase + r + 8)*E_ + gc] = v1;
        }
    }
}

// split fp32 float4 into hi/lo bf16, store to smem (stride STR2)
__device__ __forceinline__ void cvt_store72(__nv_bfloat16* smh, __nv_bfloat16* sml,
                                            int row, int colf, float4 f){
    int off = row*STR2 + colf;
    __nv_bfloat162 h01 = __floats2bfloat162_rn(f.x, f.y);
    __nv_bfloat162 h23 = __floats2bfloat162_rn(f.z, f.w);
    __nv_bfloat162 l01 = __floats2bfloat162_rn(f.x - __bfloat162float(h01.x),
                                               f.y - __bfloat162float(h01.y));
    __nv_bfloat162 l23 = __floats2bfloat162_rn(f.z - __bfloat162float(h23.x),
                                               f.w - __bfloat162float(h23.y));
    *(uint2*)(smh + off) = make_uint2(*(uint32_t*)&h01, *(uint32_t*)&h23);
    *(uint2*)(sml + off) = make_uint2(*(uint32_t*)&l01, *(uint32_t*)&l23);
}

// ---------------- 2. QK^T (HMMA split-bf16) ----------------
__global__ __launch_bounds__(256) void qk_mma()
{
    __shared__ __align__(16) __nv_bfloat16 Qh[64*STR2], Ql[64*STR2];
    __shared__ __align__(16) __nv_bfloat16 Kh[64*STR2], Kl[64*STR2];

    int b = blockIdx.x, tt = blockIdx.y;
    int tid = threadIdx.x, lane = tid & 31, wid = tid >> 5;
    const float* qb = g_q + (size_t)b*L_*HD_;
    const float* kb = g_k + (size_t)b*L_*HD_;

    #pragma unroll
    for (int i = 0; i < 4; i++){
        int idx = i*256 + tid;
        int r = idx >> 4, c = (idx & 15) * 4;
        int tg = tt*64 + r;
        float4 v = make_float4(0.f,0.f,0.f,0.f);
        if (tg < L_) v = *(const float4*)&qb[(size_t)tg*HD_ + c];
        cvt_store72(Qh, Ql, r, c, v);
    }

    int wm = (wid & 3) * 16, wn = (wid >> 2) * 32;
    uint32_t aQh = smem_u32(Qh) + (uint32_t)((wm + (lane & 15))*144 + (lane >> 4)*16);
    uint32_t aQl = smem_u32(Ql) + (uint32_t)((wm + (lane & 15))*144 + (lane >> 4)*16);
    int rowB = wn + (lane & 7) + ((lane >> 4) & 1)*8;
    uint32_t aKh = smem_u32(Kh) + (uint32_t)(rowB*144 + ((lane >> 3) & 1)*16);
    uint32_t aKl = smem_u32(Kl) + (uint32_t)(rowB*144 + ((lane >> 3) & 1)*16);

    for (int ts = 0; ts < 4; ts++){
        __syncthreads();
        #pragma unroll
        for (int i = 0; i < 4; i++){
            int idx = i*256 + tid;
            int r = idx >> 4, c = (idx & 15) * 4;
            int sg = ts*64 + r;
            float4 v = make_float4(0.f,0.f,0.f,0.f);
            if (sg < L_) v = *(const float4*)&kb[(size_t)sg*HD_ + c];
            cvt_store72(Kh, Kl, r, c, v);
        }
        __syncthreads();

        float acc[4][4];
        #pragma unroll
        for (int i=0;i<4;i++)
            #pragma unroll
            for (int j=0;j<4;j++) acc[i][j] = 0.f;

        #pragma unroll
        for (int ks = 0; ks < 4; ks++){
            uint32_t ah[4], al[4];
            ldsm_x4(ah, aQh + ks*32);
            ldsm_x4(al, aQl + ks*32);
            #pragma unroll
            for (int q = 0; q < 2; q++){
                uint32_t bh[4], bl[4];
                ldsm_x4(bh, aKh + ks*32 + q*16*144);
                ldsm_x4(bl, aKl + ks*32 + q*16*144);
                mma_bf16(acc[2*q],   ah, bh);
                mma_bf16(acc[2*q+1], ah, bh+2);
                mma_bf16(acc[2*q],   ah, bl);
                mma_bf16(acc[2*q+1], ah, bl+2);
                mma_bf16(acc[2*q],   al, bh);
                mma_bf16(acc[2*q+1], al, bh+2);
            }
        }

        int t0 = tt*64 + wm + (lane >> 2);
        int t1 = t0 + 8;
        #pragma unroll
        for (int ni = 0; ni < 4; ni++){
            int s = ts*64 + wn + ni*8 + (lane & 3)*2;
            if (s >= L_) continue;
            bool two = (s + 1 < L_);
            if (t0 < L_){
                int slot = (t0==0) ? 0 : (t0 + NS_);
                float* dst = &g_attn[((size_t)b*LT_ + slot)*LP_ + s];
                if (two) *(float2*)dst = make_float2(acc[ni][0], acc[ni][1]);
                else     dst[0] = acc[ni][0];
            }
            if (t1 < L_){
                int slot = (t1==0) ? 0 : (t1 + NS_);
                float* dst = &g_attn[((size_t)b*LT_ + slot)*LP_ + s];
                if (two) *(float2*)dst = make_float2(acc[ni][2], acc[ni][3]);
                else     dst[0] = acc[ni][2];
            }
        }
    }
}

// ---------------- 5. AV (HMMA split-bf16), writes split bf16 X ----------------
__global__ __launch_bounds__(256) void av_mma()
{
    __shared__ __align__(16) __nv_bfloat16 Ah[64*STR2], Al[64*STR2];
    __shared__ __align__(16) __nv_bfloat16 Vh[64*STR2], Vl[64*STR2];

    int b = blockIdx.x, tT = blockIdx.y;
    int tid = threadIdx.x, lane = tid & 31, wid = tid >> 5;
    const float* attn_b = g_attn + (size_t)b*LT_*LP_;
    const float* vb     = g_v    + (size_t)b*L_*HD_;

    int wm = (wid & 3) * 16, wn = (wid >> 2) * 32;
    uint32_t aAh = smem_u32(Ah) + (uint32_t)((wm + (lane & 15))*144 + (lane >> 4)*16);
    uint32_t aAl = smem_u32(Al) + (uint32_t)((wm + (lane & 15))*144 + (lane >> 4)*16);
    int rowB = wn + (lane & 7) + ((lane >> 4) & 1)*8;
    uint32_t aVh = smem_u32(Vh) + (uint32_t)(rowB*144 + ((lane >> 3) & 1)*16);
    uint32_t aVl = smem_u32(Vl) + (uint32_t)(rowB*144 + ((lane >> 3) & 1)*16);

    float acc[4][4];
    #pragma unroll
    for (int i=0;i<4;i++)
        #pragma unroll
        for (int j=0;j<4;j++) acc[i][j] = 0.f;

    for (int s0 = 0; s0 < L_; s0 += 64){
        __syncthreads();
        #pragma unroll
        for (int i = 0; i < 4; i++){
            int idx = i*256 + tid;
            int r = idx >> 4, c = (idx & 15) * 4;
            int t = tT*64 + r, s = s0 + c;
            float4 v = make_float4(0.f,0.f,0.f,0.f);
            if (t < LT_ && s + 3 < LP_) v = *(const float4*)&attn_b[(size_t)t*LP_ + s];
            cvt_store72(Ah, Al, r, c, v);
        }
        #pragma unroll
        for (int i = 0; i < 4; i++){
            int idx = i*256 + tid;
            int r = idx >> 4, c = (idx & 15) * 4;
            int sv = s0 + r;
            float4 v = make_float4(0.f,0.f,0.f,0.f);
            if (sv < L_) v = *(const float4*)&vb[(size_t)sv*HD_ + c];
            float vv[4] = {v.x, v.y, v.z, v.w};
            #pragma unroll
            for (int j = 0; j < 4; j++){
                __nv_bfloat16 h = __float2bfloat16(vv[j]);
                float lo = vv[j] - __bfloat162float(h);
                Vh[(c+j)*STR2 + r] = h;
                Vl[(c+j)*STR2 + r] = __float2bfloat16(lo);
            }
        }
        __syncthreads();

        #pragma unroll
        for (int ks = 0; ks < 4; ks++){
            uint32_t ah[4], al[4];
            ldsm_x4(ah, aAh + ks*32);
            ldsm_x4(al, aAl + ks*32);
            #pragma unroll
            for (int q = 0; q < 2; q++){
                uint32_t bh[4], bl[4];
                ldsm_x4(bh, aVh + ks*32 + q*16*144);
                ldsm_x4(bl, aVl + ks*32 + q*16*144);
                mma_bf16(acc[2*q],   ah, bh);
                mma_bf16(acc[2*q+1], ah, bh+2);
                mma_bf16(acc[2*q],   ah, bl);
                mma_bf16(acc[2*q+1], ah, bl+2);
                mma_bf16(acc[2*q],   al, bh);
                mma_bf16(acc[2*q+1], al, bh+2);
            }
        }
    }

    int n = b / H_, h = b % H_;
    int t0 = tT*64 + wm + (lane >> 2);
    int t1 = t0 + 8;
    #pragma unroll
    for (int ni = 0; ni < 4; ni++){
        int d = wn + ni*8 + (lane & 3)*2;
        #pragma unroll
        for (int half = 0; half < 2; half++){
            int t = half ? t1 : t0;
            if (t >= LT_) continue;
            float x0 = acc[ni][half*2], x1 = acc[ni][half*2+1];
            __nv_bfloat162 hh = __floats2bfloat162_rn(x0, x1);
            __nv_bfloat162 ll = __floats2bfloat162_rn(x0 - __bfloat162float(hh.x),
                                                      x1 - __bfloat162float(hh.y));
            size_t off = ((size_t)t*NB_ + n)*E_ + h*HD_ + d;
            *(uint32_t*)&g_xh[off] = *(uint32_t*)&hh;
            *(uint32_t*)&g_xl[off] = *(uint32_t*)&ll;
        }
    }
}

// ---------------- threefry2x32 (bit-exact JAX, partitionable) ----------------
__device__ __forceinline__ uint32_t rotl32(uint32_t x, int r){ return (x<<r)|(x>>(32-r)); }

__device__ __forceinline__ void tf2x32(uint32_t k0, uint32_t k1, uint32_t x0, uint32_t x1,
                                       uint32_t &o0, uint32_t &o1)
{
    uint32_t ks2 = k0 ^ k1 ^ 0x1BD11BDAu;
#define TFR(r) { x0 += x1; x1 = rotl32(x1, (r)); x1 ^= x0; }
    x0 += k0; x1 += k1;
    TFR(13) TFR(15) TFR(26) TFR(6)
    x0 += k1;  x1 += ks2 + 1u;
    TFR(17) TFR(29) TFR(16) TFR(24)
    x0 += ks2; x1 += k0 + 2u;
    TFR(13) TFR(15) TFR(26) TFR(6)
    x0 += k0;  x1 += k1 + 3u;
    TFR(17) TFR(29) TFR(16) TFR(24)
    x0 += k1;  x1 += ks2 + 4u;
    TFR(13) TFR(15) TFR(26) TFR(6)
    x0 += ks2; x1 += k0 + 5u;
#undef TFR
    o0 = x0; o1 = x1;
}

__device__ __forceinline__ uint32_t rbits32(uint32_t ka, uint32_t kb, uint32_t i){
    uint32_t o0, o1;
    tf2x32(ka, kb, 0u, i, o0, o1);
    return o0 ^ o1;
}

__device__ __forceinline__ float u01(uint32_t bits){
    return __uint_as_float((bits >> 9) | 0x3f800000u) - 1.0f;
}

__device__ __forceinline__ float blockSum256(float v, float* red){
    #pragma unroll
    for (int o=16;o>0;o>>=1) v += __shfl_xor_sync(0xffffffffu, v, o);
    __syncthreads();
    if ((threadIdx.x & 31) == 0) red[threadIdx.x >> 5] = v;
    __syncthreads();
    float s = red[0];
    #pragma unroll
    for (int i=1;i<8;i++) s += red[i];
    return s;
}

// ---------------- 3. random rows ----------------
__global__ __launch_bounds__(256) void rand_kernel()
{
    int b   = blockIdx.x;
    int tid = threadIdx.x;
    __shared__ float u[L_];
    __shared__ float cosv[NS_], sinv[NS_];
    __shared__ float red[8];
    __shared__ float norm_sh;

    uint32_t k1a, k1b, k2a, k2b;
    tf2x32(0u, 1234u, 0u, 0u, k1a, k1b);
    tf2x32(0u, 1234u, 0u, 1u, k2a, k2b);

    if (tid < NS_) {
        float f = u01(rbits32(k2a, k2b, (uint32_t)tid));
        float c = f * (0.9f - 0.7f) + 0.7f;
        cosv[tid] = c;
        sinv[tid] = sqrtf(1.0f - c*c);
    }

    float c = 0.f;
    if (tid < L_) c = g_attn[(size_t)b*LT_*LP_ + tid];
    float ss = blockSum256(c*c, red);
    if (tid == 0) norm_sh = sqrtf(ss);
    __syncthreads();
    float norm = norm_sh;
    float nden = fmaxf(norm, 1e-12f);
    if (tid < L_) u[tid] = c / nden;
    __syncthreads();

    for (int n=0; n<NS_; n++){
        float r = 0.f;
        if (tid < L_){
            uint32_t idx = ((uint32_t)n*1536u + (uint32_t)b)*197u + (uint32_t)tid;
            float f = u01(rbits32(k1a, k1b, idx));
            r = f * 2.0f - 1.0f;
        }
        float a = blockSum256((tid < L_) ? r*u[tid] : 0.f, red);
        float t = 0.f;
        if (tid < L_) t = r - a*u[tid];
        float ts = blockSum256(t*t, red);
        float inv = 1.0f / fmaxf(sqrtf(ts), 1e-12f);
        if (tid < L_){
            float w = cosv[n]*u[tid] + sinv[n]*(t*inv);
            g_attn[((size_t)b*LT_ + 1 + n)*LP_ + tid] = w * norm;
        }
    }
}

// ---------------- 4. softmax: warp per row ----------------
__global__ __launch_bounds__(256) void softmax_kernel()
{
    int wid = threadIdx.x >> 5, lid = threadIdx.x & 31;
    size_t row = (size_t)blockIdx.x * 8 + wid;
    float* p = g_attn + row * LP_;

    float v[7];
    float m = -3.402823466e38f;
    #pragma unroll
    for (int i = 0; i < 7; i++){
        int idx = i*32 + lid;
        v[i] = (idx < L_) ? p[idx] : -3.402823466e38f;
        m = fmaxf(m, v[i]);
    }
    #pragma unroll
    for (int o=16;o>0;o>>=1) m = fmaxf(m, __shfl_xor_sync(0xffffffffu, m, o));
    float s = 0.f;
    #pragma unroll
    for (int i = 0; i < 7; i++){
        v[i] = expf(v[i] - m);
        s += v[i];
    }
    #pragma unroll
    for (int o=16;o>0;o>>=1) s += __shfl_xor_sync(0xffffffffu, s, o);
    float inv = 1.0f / s;
    #pragma unroll
    for (int i = 0; i < 7; i++){
        int idx = i*32 + lid;
        if (idx < L_) p[idx] = v[i] * inv;
        else if (idx < LP_) p[idx] = 0.f;
    }
}

// ---------------- 7. attn_weights = mean over heads ----------------
__global__ __launch_bounds__(256) void mean_kernel(float* __restrict__ aw)
{
    int idx = blockIdx.x * 256 + threadIdx.x;
    if (idx >= AW_ELEMS) return;
    int s = idx % L_;
    int t = (idx / L_) % LT_;
    int n = idx / (L_ * LT_);
    float sum = 0.f;
    #pragma unroll
    for (int h=0; h<H_; h++)
        sum += g_attn[(((size_t)(n*H_ + h))*LT_ + t)*LP_ + s];
    aw[idx] = sum * (1.0f/12.0f);
}

// ---------------- launch ----------------
extern "C" void kernel_launch(void* const* d_in, const int* in_sizes, int n_in,
                              void* d_out, int out_size)
{
    const float* q   = (const float*)d_in[0];
    const float* k   = (const float*)d_in[1];
    const float* v   = (const float*)d_in[2];
    const float* ipw = (const float*)d_in[3];
    const float* ipb = (const float*)d_in[4];
    const float* opw = (const float*)d_in[5];
    const float* opb = (const float*)d_in[6];
    float* out = (float*)d_out;

    static __nv_bfloat16 *inh_p = nullptr, *inl_p = nullptr, *wh_p = nullptr, *wl_p = nullptr;
    __nv_bfloat16 *inh, *inl, *wh, *wl;
    cudaGetSymbolAddress((void**)&inh, g_in_h);
    cudaGetSymbolAddress((void**)&inl, g_in_l);
    cudaGetSymbolAddress((void**)&wh,  g_w_h);
    cudaGetSymbolAddress((void**)&wl,  g_w_l);

    cudaFuncSetAttribute(proj_tc, cudaFuncAttributeMaxDynamicSharedMemorySize, SMEM_GEMM);
    cudaFuncSetAttribute(out_tc,  cudaFuncAttributeMaxDynamicSharedMemorySize, SMEM_GEMM);

    const int n4in = IN_ELEMS/4;
    split_kernel<<<(n4in+255)/256, 256>>>(q, inh, inl, n4in);
    split_kernel<<<(n4in+255)/256, 256>>>(k, inh + IN_ELEMS, inl + IN_ELEMS, n4in);
    split_kernel<<<(n4in+255)/256, 256>>>(v, inh + 2*IN_ELEMS, inl + 2*IN_ELEMS, n4in);
    split_kernel<<<(3*W_ELEMS/4+255)/256, 256>>>(ipw, wh, wl, 3*W_ELEMS/4);
    split_kernel<<<(W_ELEMS/4+255)/256, 256>>>(opw, wh + 3*W_ELEMS, wl + 3*W_ELEMS, W_ELEMS/4);

    proj_tc<<<dim3(6,197,3), 256, SMEM_GEMM>>>(ipb);
    qk_mma<<<dim3(1536,4), 256>>>();
    rand_kernel<<<1536, 256>>>();
    softmax_kernel<<<(B_*LT_)/8, 256>>>();
    av_mma<<<dim3(1536,5), 256>>>();
    out_tc<<<dim3(6,257), 256, SMEM_GEMM>>>(opb, out);
    mean_kernel<<<(AW_ELEMS + 255)/256, 256>>>(out + OUT_ELEMS);
}

// round 8
// speedup vs baseline: 1.2557x; 1.2557x over previous
#include <cuda_runtime.h>
#include <cuda_fp16.h>
#include <cstdint>

#define L_   197
#define LP_  200
#define NB_  128
#define E_   768
#define H_   12
#define HD_  64
#define B_   1536
#define NS_  60
#define LT_  257
#define OUT_ELEMS 25264128
#define AW_ELEMS  6480512

#define STRH 40        // proj/out smem row stride in halves (80 B)
#define STR2 72        // qk/av smem row stride in halves (144 B)

#define IN_ELEMS 19365888        // 25216*768
#define W_ELEMS  589824          // 768*768
#define DESCALE 0.00390625f      // 2^-8

// ---------------- scratch ----------------
__device__ float g_q[19365888];
__device__ float g_k[19365888];
__device__ float g_v[19365888];
__device__ float g_attn[78950400];       // (B, LT, LP_)
__device__ __half g_ah[3*IN_ELEMS];      // inputs rounded to fp16
__device__ __half g_wh[4*W_ELEMS];       // weights*256 hi
__device__ __half g_wl[4*W_ELEMS];       // weights*256 lo
__device__ __half g_xh[OUT_ELEMS];       // AV output, fp16

// ================= helpers =================
__device__ __forceinline__ uint32_t smem_u32(const void* p){
    return (uint32_t)__cvta_generic_to_shared(p);
}
__device__ __forceinline__ void ldsm_x4(uint32_t* r, uint32_t addr){
    asm volatile("ldmatrix.sync.aligned.m8n8.x4.shared.b16 {%0,%1,%2,%3}, [%4];"
        : "=r"(r[0]),"=r"(r[1]),"=r"(r[2]),"=r"(r[3]) : "r"(addr));
}
__device__ __forceinline__ void mma_f16(float* d, const uint32_t* a, const uint32_t* b){
    asm volatile("mma.sync.aligned.m16n8k16.row.col.f32.f16.f16.f32 "
        "{%0,%1,%2,%3}, {%4,%5,%6,%7}, {%8,%9}, {%0,%1,%2,%3};"
        : "+f"(d[0]),"+f"(d[1]),"+f"(d[2]),"+f"(d[3])
        : "r"(a[0]),"r"(a[1]),"r"(a[2]),"r"(a[3]), "r"(b[0]),"r"(b[1]));
}

// ---------------- 0a. round fp32 -> fp16 ----------------
__global__ __launch_bounds__(256) void round_kernel(
    const float* __restrict__ src, __half* __restrict__ dst, int n4)
{
    int i = blockIdx.x * 256 + threadIdx.x;
    if (i >= n4) return;
    float4 f = ((const float4*)src)[i];
    __half2 h01 = __floats2half2_rn(f.x, f.y);
    __half2 h23 = __floats2half2_rn(f.z, f.w);
    *(uint2*)(dst + 4*(size_t)i) = make_uint2(*(uint32_t*)&h01, *(uint32_t*)&h23);
}

// ---------------- 0b. split (256*w) -> fp16 hi/lo ----------------
__global__ __launch_bounds__(256) void splitw_kernel(
    const float* __restrict__ src, __half* __restrict__ dh,
    __half* __restrict__ dl, int n4)
{
    int i = blockIdx.x * 256 + threadIdx.x;
    if (i >= n4) return;
    float4 f = ((const float4*)src)[i];
    float sx = f.x*256.f, sy = f.y*256.f, sz = f.z*256.f, sw = f.w*256.f;
    __half2 h01 = __floats2half2_rn(sx, sy);
    __half2 h23 = __floats2half2_rn(sz, sw);
    __half2 l01 = __floats2half2_rn(sx - __half2float(h01.x), sy - __half2float(h01.y));
    __half2 l23 = __floats2half2_rn(sz - __half2float(h23.x), sw - __half2float(h23.y));
    *(uint2*)(dh + 4*(size_t)i) = make_uint2(*(uint32_t*)&h01, *(uint32_t*)&h23);
    *(uint2*)(dl + 4*(size_t)i) = make_uint2(*(uint32_t*)&l01, *(uint32_t*)&l23);
}

// ---- GEMM body: C(128x128) = A(128x768,fp16) * (Bh+Bl)(128x768)^T, K-chunks of 32 ----
__device__ __forceinline__ void gemm_body16(
    const __half* __restrict__ Ag, const __half* __restrict__ Bh,
    const __half* __restrict__ Bl,
    __half* sA, __half* sBh, __half* sBl,
    float acc[2][8][4], int tid)
{
    int lane = tid & 31, wid = tid >> 5;
    int wm = (wid & 3) * 32, wn = (wid >> 2) * 64;

    uint32_t aA = smem_u32(sA) + (uint32_t)((wm + (lane & 15))*80 + (lane >> 4)*16);
    int rowB = wn + (lane & 7) + ((lane >> 4) & 1)*8;
    uint32_t oBh = smem_u32(sBh) + (uint32_t)(rowB*80 + ((lane >> 3) & 1)*16);
    uint32_t oBl = smem_u32(sBl) + (uint32_t)(rowB*80 + ((lane >> 3) & 1)*16);

    for (int ch = 0; ch < 24; ch++){
        int kBase = ch * 32;
        uint4 va[2], vh[2], vl[2];
        int rr[2], ss[2];
        #pragma unroll
        for (int j = 0; j < 2; j++){
            int idx = j*256 + tid;          // < 512
            rr[j] = idx >> 2;
            ss[j] = (idx & 3) * 8;          // half offset within 32
            size_t go = (size_t)rr[j]*E_ + kBase + ss[j];
            va[j] = *(const uint4*)(Ag + go);
            vh[j] = *(const uint4*)(Bh + go);
            vl[j] = *(const uint4*)(Bl + go);
        }
        __syncthreads();
        #pragma unroll
        for (int j = 0; j < 2; j++){
            int so = rr[j]*STRH + ss[j];
            *(uint4*)(sA  + so) = va[j];
            *(uint4*)(sBh + so) = vh[j];
            *(uint4*)(sBl + so) = vl[j];
        }
        __syncthreads();

        #pragma unroll
        for (int ks = 0; ks < 2; ks++){
            uint32_t a0[4], a1[4];
            ldsm_x4(a0, aA + ks*32);
            ldsm_x4(a1, aA + ks*32 + 16*80);
            #pragma unroll
            for (int q = 0; q < 4; q++){
                uint32_t bh[4], bl[4];
                ldsm_x4(bh, oBh + ks*32 + q*16*80);
                ldsm_x4(bl, oBl + ks*32 + q*16*80);
                mma_f16(acc[0][2*q],   a0, bh);
                mma_f16(acc[0][2*q+1], a0, bh+2);
                mma_f16(acc[0][2*q],   a0, bl);
                mma_f16(acc[0][2*q+1], a0, bl+2);
                mma_f16(acc[1][2*q],   a1, bh);
                mma_f16(acc[1][2*q+1], a1, bh+2);
                mma_f16(acc[1][2*q],   a1, bl);
                mma_f16(acc[1][2*q+1], a1, bl+2);
            }
        }
    }
}

// ---------------- 1. QKV projection ----------------
__global__ __launch_bounds__(256, 2) void proj_tc(const float* __restrict__ bias)
{
    __shared__ __align__(16) __half sA[128*STRH], sBh[128*STRH], sBl[128*STRH];

    int tid = threadIdx.x, lane = tid & 31, wid = tid >> 5;
    int p = blockIdx.z;
    const __half* Ah = g_ah + (size_t)p*IN_ELEMS;
    const __half* Bh = g_wh + (size_t)p*W_ELEMS;
    const __half* Bl = g_wl + (size_t)p*W_ELEMS;
    const float* bp = bias + (size_t)p*E_;
    float* outp     = (p==0) ? g_q : ((p==1) ? g_k : g_v);
    float scale     = (p==0) ? 0.125f : 1.0f;

    int l = blockIdx.y;
    int nBase = blockIdx.x * 128;
    size_t mBase = (size_t)l * 128;

    float acc[2][8][4];
    #pragma unroll
    for (int i=0;i<2;i++)
        #pragma unroll
        for (int j=0;j<8;j++)
            #pragma unroll
            for (int c=0;c<4;c++) acc[i][j][c] = 0.f;

    gemm_body16(Ah + mBase*E_, Bh + (size_t)nBase*E_, Bl + (size_t)nBase*E_,
                sA, sBh, sBl, acc, tid);

    int wm = (wid & 3) * 32, wn = (wid >> 2) * 64;
    #pragma unroll
    for (int mi = 0; mi < 2; mi++){
        int r = wm + mi*16 + (lane >> 2);
        #pragma unroll
        for (int ni = 0; ni < 8; ni++){
            int col = wn + ni*8 + (lane & 3)*2;
            int gc  = nBase + col;
            int h = gc >> 6, d = gc & 63;
            float b0 = bp[gc], b1 = bp[gc+1];
            float2 v0 = make_float2((acc[mi][ni][0]*DESCALE + b0)*scale,
                                    (acc[mi][ni][1]*DESCALE + b1)*scale);
            float2 v1 = make_float2((acc[mi][ni][2]*DESCALE + b0)*scale,
                                    (acc[mi][ni][3]*DESCALE + b1)*scale);
            *(float2*)&outp[(((size_t)(r*H_ + h))*L_ + l)*HD_ + d] = v0;
            *(float2*)&outp[(((size_t)((r+8)*H_ + h))*L_ + l)*HD_ + d] = v1;
        }
    }
}

// ---------------- 6. out projection ----------------
__global__ __launch_bounds__(256, 2) void out_tc(
    const float* __restrict__ bias, float* __restrict__ outp)
{
    __shared__ __align__(16) __half sA[128*STRH], sBh[128*STRH], sBl[128*STRH];

    int tid = threadIdx.x, lane = tid & 31, wid = tid >> 5;
    size_t mBase = (size_t)blockIdx.y * 128;
    int nBase = blockIdx.x * 128;

    float acc[2][8][4];
    #pragma unroll
    for (int i=0;i<2;i++)
        #pragma unroll
        for (int j=0;j<8;j++)
            #pragma unroll
            for (int c=0;c<4;c++) acc[i][j][c] = 0.f;

    gemm_body16(g_xh + mBase*E_,
                g_wh + (size_t)3*W_ELEMS + (size_t)nBase*E_,
                g_wl + (size_t)3*W_ELEMS + (size_t)nBase*E_,
                sA, sBh, sBl, acc, tid);

    int wm = (wid & 3) * 32, wn = (wid >> 2) * 64;
    #pragma unroll
    for (int mi = 0; mi < 2; mi++){
        int r = wm + mi*16 + (lane >> 2);
        #pragma unroll
        for (int ni = 0; ni < 8; ni++){
            int col = wn + ni*8 + (lane & 3)*2;
            int gc  = nBase + col;
            float b0 = bias[gc], b1 = bias[gc+1];
            float2 v0 = make_float2(acc[mi][ni][0]*DESCALE + b0,
                                    acc[mi][ni][1]*DESCALE + b1);
            float2 v1 = make_float2(acc[mi][ni][2]*DESCALE + b0,
                                    acc[mi][ni][3]*DESCALE + b1);
            *(float2*)&outp[(mBase + r)*E_ + gc] = v0;
            *(float2*)&outp[(mBase + r + 8)*E_ + gc] = v1;
        }
    }
}

// round fp32x4 -> fp16, store to smem (stride STR2)
__device__ __forceinline__ void round72(__half* sm, int row, int colf, float4 f){
    __half2 h01 = __floats2half2_rn(f.x, f.y);
    __half2 h23 = __floats2half2_rn(f.z, f.w);
    *(uint2*)(sm + row*STR2 + colf) = make_uint2(*(uint32_t*)&h01, *(uint32_t*)&h23);
}
// split (256*f) -> hi/lo fp16, store to smem (stride STR2)
__device__ __forceinline__ void split72(__half* smh, __half* sml, int row, int colf, float4 f){
    float sx = f.x*256.f, sy = f.y*256.f, sz = f.z*256.f, sw = f.w*256.f;
    __half2 h01 = __floats2half2_rn(sx, sy);
    __half2 h23 = __floats2half2_rn(sz, sw);
    __half2 l01 = __floats2half2_rn(sx - __half2float(h01.x), sy - __half2float(h01.y));
    __half2 l23 = __floats2half2_rn(sz - __half2float(h23.x), sw - __half2float(h23.y));
    int off = row*STR2 + colf;
    *(uint2*)(smh + off) = make_uint2(*(uint32_t*)&h01, *(uint32_t*)&h23);
    *(uint2*)(sml + off) = make_uint2(*(uint32_t*)&l01, *(uint32_t*)&l23);
}

// ---------------- 2. QK^T ----------------
__global__ __launch_bounds__(256) void qk_mma()
{
    __shared__ __align__(16) __half Qs[64*STR2];
    __shared__ __align__(16) __half Kh[64*STR2], Kl[64*STR2];

    int b = blockIdx.x, tt = blockIdx.y;
    int tid = threadIdx.x, lane = tid & 31, wid = tid >> 5;
    const float* qb = g_q + (size_t)b*L_*HD_;
    const float* kb = g_k + (size_t)b*L_*HD_;

    #pragma unroll
    for (int i = 0; i < 4; i++){
        int idx = i*256 + tid;
        int r = idx >> 4, c = (idx & 15) * 4;
        int tg = tt*64 + r;
        float4 v = make_float4(0.f,0.f,0.f,0.f);
        if (tg < L_) v = *(const float4*)&qb[(size_t)tg*HD_ + c];
        round72(Qs, r, c, v);
    }

    int wm = (wid & 3) * 16, wn = (wid >> 2) * 32;
    uint32_t aQ = smem_u32(Qs) + (uint32_t)((wm + (lane & 15))*144 + (lane >> 4)*16);
    int rowB = wn + (lane & 7) + ((lane >> 4) & 1)*8;
    uint32_t aKh = smem_u32(Kh) + (uint32_t)(rowB*144 + ((lane >> 3) & 1)*16);
    uint32_t aKl = smem_u32(Kl) + (uint32_t)(rowB*144 + ((lane >> 3) & 1)*16);

    for (int ts = 0; ts < 4; ts++){
        __syncthreads();
        #pragma unroll
        for (int i = 0; i < 4; i++){
            int idx = i*256 + tid;
            int r = idx >> 4, c = (idx & 15) * 4;
            int sg = ts*64 + r;
            float4 v = make_float4(0.f,0.f,0.f,0.f);
            if (sg < L_) v = *(const float4*)&kb[(size_t)sg*HD_ + c];
            split72(Kh, Kl, r, c, v);
        }
        __syncthreads();

        float acc[4][4];
        #pragma unroll
        for (int i=0;i<4;i++)
            #pragma unroll
            for (int j=0;j<4;j++) acc[i][j] = 0.f;

        #pragma unroll
        for (int ks = 0; ks < 4; ks++){
            uint32_t a[4];
            ldsm_x4(a, aQ + ks*32);
            #pragma unroll
            for (int q = 0; q < 2; q++){
                uint32_t bh[4], bl[4];
                ldsm_x4(bh, aKh + ks*32 + q*16*144);
                ldsm_x4(bl, aKl + ks*32 + q*16*144);
                mma_f16(acc[2*q],   a, bh);
                mma_f16(acc[2*q+1], a, bh+2);
                mma_f16(acc[2*q],   a, bl);
                mma_f16(acc[2*q+1], a, bl+2);
            }
        }

        int t0 = tt*64 + wm + (lane >> 2);
        int t1 = t0 + 8;
        #pragma unroll
        for (int ni = 0; ni < 4; ni++){
            int s = ts*64 + wn + ni*8 + (lane & 3)*2;
            if (s >= L_) continue;
            bool two = (s + 1 < L_);
            if (t0 < L_){
                int slot = (t0==0) ? 0 : (t0 + NS_);
                float* dst = &g_attn[((size_t)b*LT_ + slot)*LP_ + s];
                if (two) *(float2*)dst = make_float2(acc[ni][0]*DESCALE, acc[ni][1]*DESCALE);
                else     dst[0] = acc[ni][0]*DESCALE;
            }
            if (t1 < L_){
                int slot = (t1==0) ? 0 : (t1 + NS_);
                float* dst = &g_attn[((size_t)b*LT_ + slot)*LP_ + s];
                if (two) *(float2*)dst = make_float2(acc[ni][2]*DESCALE, acc[ni][3]*DESCALE);
                else     dst[0] = acc[ni][2]*DESCALE;
            }
        }
    }
}

// ---------------- 5. AV -> fp16 X ----------------
__global__ __launch_bounds__(256) void av_mma()
{
    __shared__ __align__(16) __half Ahs[64*STR2];
    __shared__ __align__(16) __half Vh[64*STR2], Vl[64*STR2];

    int b = blockIdx.x, tT = blockIdx.y;
    int tid = threadIdx.x, lane = tid & 31, wid = tid >> 5;
    const float* attn_b = g_attn + (size_t)b*LT_*LP_;
    const float* vb     = g_v    + (size_t)b*L_*HD_;

    int wm = (wid & 3) * 16, wn = (wid >> 2) * 32;
    uint32_t aA = smem_u32(Ahs) + (uint32_t)((wm + (lane & 15))*144 + (lane >> 4)*16);
    int rowB = wn + (lane & 7) + ((lane >> 4) & 1)*8;
    uint32_t aVh = smem_u32(Vh) + (uint32_t)(rowB*144 + ((lane >> 3) & 1)*16);
    uint32_t aVl = smem_u32(Vl) + (uint32_t)(rowB*144 + ((lane >> 3) & 1)*16);

    float acc[4][4];
    #pragma unroll
    for (int i=0;i<4;i++)
        #pragma unroll
        for (int j=0;j<4;j++) acc[i][j] = 0.f;

    for (int s0 = 0; s0 < L_; s0 += 64){
        __syncthreads();
        #pragma unroll
        for (int i = 0; i < 4; i++){
            int idx = i*256 + tid;
            int r = idx >> 4, c = (idx & 15) * 4;
            int t = tT*64 + r, s = s0 + c;
            float4 v = make_float4(0.f,0.f,0.f,0.f);
            if (t < LT_ && s + 3 < LP_) v = *(const float4*)&attn_b[(size_t)t*LP_ + s];
            round72(Ahs, r, c, v);
        }
        #pragma unroll
        for (int i = 0; i < 4; i++){
            int idx = i*256 + tid;
            int r = idx >> 4, c = (idx & 15) * 4;
            int sv = s0 + r;
            float4 v = make_float4(0.f,0.f,0.f,0.f);
            if (sv < L_) v = *(const float4*)&vb[(size_t)sv*HD_ + c];
            float vv[4] = {v.x, v.y, v.z, v.w};
            #pragma unroll
            for (int j = 0; j < 4; j++){
                float sfv = vv[j]*256.f;
                __half h = __float2half_rn(sfv);
                Vh[(c+j)*STR2 + r] = h;
                Vl[(c+j)*STR2 + r] = __float2half_rn(sfv - __half2float(h));
            }
        }
        __syncthreads();

        #pragma unroll
        for (int ks = 0; ks < 4; ks++){
            uint32_t a[4];
            ldsm_x4(a, aA + ks*32);
            #pragma unroll
            for (int q = 0; q < 2; q++){
                uint32_t bh[4], bl[4];
                ldsm_x4(bh, aVh + ks*32 + q*16*144);
                ldsm_x4(bl, aVl + ks*32 + q*16*144);
                mma_f16(acc[2*q],   a, bh);
                mma_f16(acc[2*q+1], a, bh+2);
                mma_f16(acc[2*q],   a, bl);
                mma_f16(acc[2*q+1], a, bl+2);
            }
        }
    }

    int n = b / H_, h = b % H_;
    int t0 = tT*64 + wm + (lane >> 2);
    int t1 = t0 + 8;
    #pragma unroll
    for (int ni = 0; ni < 4; ni++){
        int d = wn + ni*8 + (lane & 3)*2;
        #pragma unroll
        for (int half = 0; half < 2; half++){
            int t = half ? t1 : t0;
            if (t >= LT_) continue;
            __half2 hh = __floats2half2_rn(acc[ni][half*2]*DESCALE,
                                           acc[ni][half*2+1]*DESCALE);
            *(uint32_t*)&g_xh[((size_t)t*NB_ + n)*E_ + h*HD_ + d] = *(uint32_t*)&hh;
        }
    }
}

// ---------------- threefry2x32 (bit-exact JAX, partitionable) ----------------
__device__ __forceinline__ uint32_t rotl32(uint32_t x, int r){ return (x<<r)|(x>>(32-r)); }

__device__ __forceinline__ void tf2x32(uint32_t k0, uint32_t k1, uint32_t x0, uint32_t x1,
                                       uint32_t &o0, uint32_t &o1)
{
    uint32_t ks2 = k0 ^ k1 ^ 0x1BD11BDAu;
#define TFR(r) { x0 += x1; x1 = rotl32(x1, (r)); x1 ^= x0; }
    x0 += k0; x1 += k1;
    TFR(13) TFR(15) TFR(26) TFR(6)
    x0 += k1;  x1 += ks2 + 1u;
    TFR(17) TFR(29) TFR(16) TFR(24)
    x0 += ks2; x1 += k0 + 2u;
    TFR(13) TFR(15) TFR(26) TFR(6)
    x0 += k0;  x1 += k1 + 3u;
    TFR(17) TFR(29) TFR(16) TFR(24)
    x0 += k1;  x1 += ks2 + 4u;
    TFR(13) TFR(15) TFR(26) TFR(6)
    x0 += ks2; x1 += k0 + 5u;
#undef TFR
    o0 = x0; o1 = x1;
}

__device__ __forceinline__ uint32_t rbits32(uint32_t ka, uint32_t kb, uint32_t i){
    uint32_t o0, o1;
    tf2x32(ka, kb, 0u, i, o0, o1);
    return o0 ^ o1;
}

__device__ __forceinline__ float u01(uint32_t bits){
    return __uint_as_float((bits >> 9) | 0x3f800000u) - 1.0f;
}

__device__ __forceinline__ float blockSum256(float v, float* red){
    #pragma unroll
    for (int o=16;o>0;o>>=1) v += __shfl_xor_sync(0xffffffffu, v, o);
    __syncthreads();
    if ((threadIdx.x & 31) == 0) red[threadIdx.x >> 5] = v;
    __syncthreads();
    float s = red[0];
    #pragma unroll
    for (int i=1;i<8;i++) s += red[i];
    return s;
}

// ---------------- 3. random rows ----------------
__global__ __launch_bounds__(256) void rand_kernel()
{
    int b   = blockIdx.x;
    int tid = threadIdx.x;
    __shared__ float u[L_];
    __shared__ float cosv[NS_], sinv[NS_];
    __shared__ float red[8];
    __shared__ float norm_sh;

    uint32_t k1a, k1b, k2a, k2b;
    tf2x32(0u, 1234u, 0u, 0u, k1a, k1b);
    tf2x32(0u, 1234u, 0u, 1u, k2a, k2b);

    if (tid < NS_) {
        float f = u01(rbits32(k2a, k2b, (uint32_t)tid));
        float c = f * (0.9f - 0.7f) + 0.7f;
        cosv[tid] = c;
        sinv[tid] = sqrtf(1.0f - c*c);
    }

    float c = 0.f;
    if (tid < L_) c = g_attn[(size_t)b*LT_*LP_ + tid];
    float ss = blockSum256(c*c, red);
    if (tid == 0) norm_sh = sqrtf(ss);
    __syncthreads();
    float norm = norm_sh;
    float nden = fmaxf(norm, 1e-12f);
    if (tid < L_) u[tid] = c / nden;
    __syncthreads();

    for (int n=0; n<NS_; n++){
        float r = 0.f;
        if (tid < L_){
            uint32_t idx = ((uint32_t)n*1536u + (uint32_t)b)*197u + (uint32_t)tid;
            float f = u01(rbits32(k1a, k1b, idx));
            r = f * 2.0f - 1.0f;
        }
        float a = blockSum256((tid < L_) ? r*u[tid] : 0.f, red);
        float t = 0.f;
        if (tid < L_) t = r - a*u[tid];
        float ts = blockSum256(t*t, red);
        float inv = 1.0f / fmaxf(sqrtf(ts), 1e-12f);
        if (tid < L_){
            float w = cosv[n]*u[tid] + sinv[n]*(t*inv);
            g_attn[((size_t)b*LT_ + 1 + n)*LP_ + tid] = w * norm;
        }
    }
}

// ---------------- 4. softmax: warp per row ----------------
__global__ __launch_bounds__(256) void softmax_kernel()
{
    int wid = threadIdx.x >> 5, lid = threadIdx.x & 31;
    size_t row = (size_t)blockIdx.x * 8 + wid;
    float* p = g_attn + row * LP_;

    float v[7];
    float m = -3.402823466e38f;
    #pragma unroll
    for (int i = 0; i < 7; i++){
        int idx = i*32 + lid;
        v[i] = (idx < L_) ? p[idx] : -3.402823466e38f;
        m = fmaxf(m, v[i]);
    }
    #pragma unroll
    for (int o=16;o>0;o>>=1) m = fmaxf(m, __shfl_xor_sync(0xffffffffu, m, o));
    float s = 0.f;
    #pragma unroll
    for (int i = 0; i < 7; i++){
        v[i] = expf(v[i] - m);
        s += v[i];
    }
    #pragma unroll
    for (int o=16;o>0;o>>=1) s += __shfl_xor_sync(0xffffffffu, s, o);
    float inv = 1.0f / s;
    #pragma unroll
    for (int i = 0; i < 7; i++){
        int idx = i*32 + lid;
        if (idx < L_) p[idx] = v[i] * inv;
        else if (idx < LP_) p[idx] = 0.f;
    }
}

// ---------------- 7. attn_weights = mean over heads ----------------
__global__ __launch_bounds__(256) void mean_kernel(float* __restrict__ aw)
{
    int idx = blockIdx.x * 256 + threadIdx.x;
    if (idx >= AW_ELEMS) return;
    int s = idx % L_;
    int t = (idx / L_) % LT_;
    int n = idx / (L_ * LT_);
    float sum = 0.f;
    #pragma unroll
    for (int h=0; h<H_; h++)
        sum += g_attn[(((size_t)(n*H_ + h))*LT_ + t)*LP_ + s];
    aw[idx] = sum * (1.0f/12.0f);
}

// ---------------- launch ----------------
extern "C" void kernel_launch(void* const* d_in, const int* in_sizes, int n_in,
                              void* d_out, int out_size)
{
    const float* q   = (const float*)d_in[0];
    const float* k   = (const float*)d_in[1];
    const float* v   = (const float*)d_in[2];
    const float* ipw = (const float*)d_in[3];
    const float* ipb = (const float*)d_in[4];
    const float* opw = (const float*)d_in[5];
    const float* opb = (const float*)d_in[6];
    float* out = (float*)d_out;

    __half *ah, *wh, *wl;
    cudaGetSymbolAddress((void**)&ah, g_ah);
    cudaGetSymbolAddress((void**)&wh, g_wh);
    cudaGetSymbolAddress((void**)&wl, g_wl);

    const int n4in = IN_ELEMS/4;
    round_kernel<<<(n4in+255)/256, 256>>>(q, ah, n4in);
    round_kernel<<<(n4in+255)/256, 256>>>(k, ah + IN_ELEMS, n4in);
    round_kernel<<<(n4in+255)/256, 256>>>(v, ah + 2*IN_ELEMS, n4in);
    splitw_kernel<<<(3*W_ELEMS/4+255)/256, 256>>>(ipw, wh, wl, 3*W_ELEMS/4);
    splitw_kernel<<<(W_ELEMS/4+255)/256, 256>>>(opw, wh + 3*W_ELEMS, wl + 3*W_ELEMS, W_ELEMS/4);

    proj_tc<<<dim3(6,197,3), 256>>>(ipb);
    qk_mma<<<dim3(1536,4), 256>>>();
    rand_kernel<<<1536, 256>>>();
    softmax_kernel<<<(B_*LT_)/8, 256>>>();
    av_mma<<<dim3(1536,5), 256>>>();
    out_tc<<<dim3(6,257), 256>>>(opb, out);
    mean_kernel<<<(AW_ELEMS + 255)/256, 256>>>(out + OUT_ELEMS);
}